// round 5
// baseline (speedup 1.0000x reference)
#include <cuda_runtime.h>
#include <cuda_bf16.h>

// B=4, H=16, L=8192, D=64
#define BH_    64
#define H_     16
#define L_     8192
#define D_     64
#define TILE_  128                 // positions per tile (block)
#define PPW_   16                  // positions per warp
#define WPB_   8                   // warps per block
#define NT_    64                  // tiles per (b,h) chain
#define NBLK_  (BH_ * NT_)         // 4096
#define EPS_   1e-6f

// Decoupled-lookback state. flag: 0 = none, 1 = aggregate, 2 = inclusive.
__device__ int   g_ticket;
__device__ int   g_flag[NBLK_];
__device__ float g_aggr[(size_t)NBLK_ * 256];   // [128 k-sum | 128 kv-sum]
__device__ float g_incl[(size_t)NBLK_ * 256];

__device__ __forceinline__ float phi(float x) {
    return x > 0.0f ? x + 1.0f : __expf(x);
}

__global__ void la_reset() {
    int i = blockIdx.x * blockDim.x + threadIdx.x;
    if (i < NBLK_) g_flag[i] = 0;
    if (i == 0) g_ticket = 0;
}

// ---------------------------------------------------------------------------
// Fused single-pass scan. Per-position products stay in REGISTERS between the
// aggregate phase and the output phase (k,v read exactly once from DRAM).
// Warp w owns positions [w*16, w*16+16); lane owns channels 2*lane, 2*lane+1.
// ---------------------------------------------------------------------------
__global__ void __launch_bounds__(256) la_fused(
    const float* __restrict__ qp, const float* __restrict__ kp,
    const float* __restrict__ vp, const float* __restrict__ mp,
    float* __restrict__ op)
{
    __shared__ float s_k [WPB_][128];  // warp sums -> exclusive warp prefixes
    __shared__ float s_kv[WPB_][128];
    __shared__ float s_tot[256];       // tile totals   [k | kv]
    __shared__ float s_chain[256];     // chain prefix  [k | kv]
    __shared__ int   s_tile, s_msg;

    const int t = threadIdx.x;
    if (t == 0) s_tile = atomicAdd(&g_ticket, 1);
    __syncthreads();
    const int tile = s_tile;
    const int bh   = tile & (BH_ - 1);     // chain-interleaved ticket mapping
    const int ti   = tile >> 6;
    const int b    = bh >> 4;
    const int w    = t >> 5;
    const int lane = t & 31;
    const int l0   = ti * TILE_ + w * PPW_;
    const size_t base = ((size_t)bh * L_ + l0) * D_ + lane * 2;
    const float* mrow = mp + b * L_ + l0;

    // ---- Phase A: load k,v once; keep per-position contributions in regs ----
    float fk0[PPW_], fk1[PPW_], kv0[PPW_], kv1[PPW_];
    float mreg[PPW_];
    float sk0 = 0.f, sk1 = 0.f, sv0 = 0.f, sv1 = 0.f;
    #pragma unroll
    for (int i = 0; i < PPW_; ++i) {
        float2 kk = *(const float2*)(kp + base + (size_t)i * D_);
        float2 vv = *(const float2*)(vp + base + (size_t)i * D_);
        float  m  = mrow[i];
        mreg[i] = m;
        float a0 = phi(kk.x) * m, a1 = phi(kk.y) * m;
        float c0 = a0 * (vv.x * m), c1 = a1 * (vv.y * m);
        fk0[i] = a0; fk1[i] = a1; kv0[i] = c0; kv1[i] = c1;
        sk0 += a0; sk1 += a1; sv0 += c0; sv1 += c1;
    }
    *(float2*)&s_k [w][2 * lane] = make_float2(sk0, sk1);
    *(float2*)&s_kv[w][2 * lane] = make_float2(sv0, sv1);
    __syncthreads();

    // ---- Intra-tile scan over the 8 warps (t<128: k, t>=128: kv) ----
    {
        float run = 0.f;
        if (t < 128) {
            const int c = t;
            #pragma unroll
            for (int g2 = 0; g2 < WPB_; ++g2) {
                float x = s_k[g2][c]; s_k[g2][c] = run; run += x;
            }
        } else {
            const int c = t - 128;
            #pragma unroll
            for (int g2 = 0; g2 < WPB_; ++g2) {
                float x = s_kv[g2][c]; s_kv[g2][c] = run; run += x;
            }
        }
        s_tot[t] = run;
        if (ti > 0) g_aggr[(size_t)tile * 256 + t] = run;
    }
    __syncthreads();
    if (ti > 0) {
        __threadfence();
        if (t == 0) atomicExch(&g_flag[tile], 1);
    }

    // ---- Decoupled lookback (single flag per tile; thread 0 polls) ----
    s_chain[t] = 0.f;
    if (ti > 0) {
        volatile int* vf = (volatile int*)g_flag;
        int p = tile - BH_;
        for (;;) {
            if (t == 0) {
                int f;
                while ((f = vf[p]) == 0) __nanosleep(64);
                s_msg = f;
            }
            __syncthreads();
            const int f = s_msg;
            __threadfence();   // acquire: order payload reads after flag read
            if (f == 2) {
                s_chain[t] += g_incl[(size_t)p * 256 + t];
                break;
            }
            s_chain[t] += g_aggr[(size_t)p * 256 + t];
            p -= BH_;
            __syncthreads();
        }
    }
    __syncthreads();

    // ---- Publish inclusive prefix for successors ----
    g_incl[(size_t)tile * 256 + t] = s_chain[t] + s_tot[t];
    __syncthreads();
    __threadfence();
    if (t == 0) atomicExch(&g_flag[tile], 2);

    // ---- Phase C: finish scan in registers, compute z, emit output ----
    float2 pk  = make_float2(s_chain[2 * lane]     + s_k [w][2 * lane],
                             s_chain[2 * lane + 1] + s_k [w][2 * lane + 1]);
    float2 pkv = make_float2(s_chain[128 + 2 * lane]     + s_kv[w][2 * lane],
                             s_chain[128 + 2 * lane + 1] + s_kv[w][2 * lane + 1]);

    #pragma unroll
    for (int i = 0; i < PPW_; ++i) {
        pk.x  += fk0[i]; pk.y  += fk1[i];
        pkv.x += kv0[i]; pkv.y += kv1[i];
        float2 qq = *(const float2*)(qp + base + (size_t)i * D_);
        float q0 = phi(qq.x), q1 = phi(qq.y);
        float z = q0 * pk.x + q1 * pk.y;
        z += __shfl_xor_sync(0xffffffffu, z, 16);
        z += __shfl_xor_sync(0xffffffffu, z, 8);
        z += __shfl_xor_sync(0xffffffffu, z, 4);
        z += __shfl_xor_sync(0xffffffffu, z, 2);
        z += __shfl_xor_sync(0xffffffffu, z, 1);
        z = (z + EPS_) * mreg[i];
        float rz = 1.0f / z;
        float2 o = make_float2(q0 * pkv.x * rz, q1 * pkv.y * rz);
        *(float2*)(op + base + (size_t)i * D_) = o;
    }
}

// ---------------------------------------------------------------------------
extern "C" void kernel_launch(void* const* d_in, const int* in_sizes, int n_in,
                              void* d_out, int out_size)
{
    const float* q = (const float*)d_in[0];
    const float* k = (const float*)d_in[1];
    const float* v = (const float*)d_in[2];
    const float* m = (const float*)d_in[3];
    float* out = (float*)d_out;

    la_reset<<<(NBLK_ + 255) / 256, 256>>>();
    la_fused<<<NBLK_, 256>>>(q, k, v, m, out);
}

// round 6
// speedup vs baseline: 1.5411x; 1.5411x over previous
#include <cuda_runtime.h>
#include <cuda_bf16.h>

// B=4, H=16, L=8192, D=64
#define BH_    64
#define H_     16
#define L_     8192
#define D_     64
#define TILE_  64                  // positions per tile (block)
#define PPW_   8                   // positions per warp
#define WPB_   8                   // warps per block
#define NT_    128                 // tiles per (b,h) chain
#define NBLK_  (BH_ * NT_)         // 8192
#define EPS_   1e-6f

// Decoupled-lookback state. flag: 0 = none, 1 = aggregate, 2 = inclusive.
__device__ int   g_ticket;
__device__ int   g_flag[NBLK_];
__device__ float g_aggr[(size_t)NBLK_ * 128];   // [64 k-sum | 64 kv-sum]
__device__ float g_incl[(size_t)NBLK_ * 128];

__device__ __forceinline__ float phi(float x) {
    return x > 0.0f ? x + 1.0f : __expf(x);
}

__global__ void la_reset() {
    int i = blockIdx.x * blockDim.x + threadIdx.x;
    if (i < NBLK_) g_flag[i] = 0;
    if (i == 0) g_ticket = 0;
}

// ---------------------------------------------------------------------------
// Fused single-pass scan, small tiles. Phase A streams k,v from DRAM and
// computes warp sums; phase C re-reads the same 32KB tile from L2 (resident
// footprint ~23MB << 126MB L2). Warp w owns positions [w*8, w*8+8); lane owns
// channels 2*lane, 2*lane+1. Scan channel space: c<64 = k-state, c>=64 = kv.
// ---------------------------------------------------------------------------
__global__ void __launch_bounds__(256, 5) la_fused(
    const float* __restrict__ qp, const float* __restrict__ kp,
    const float* __restrict__ vp, const float* __restrict__ mp,
    float* __restrict__ op)
{
    __shared__ float s_warp[WPB_][128];  // warp sums -> exclusive warp prefixes
    __shared__ float s_tot[128];         // tile totals
    __shared__ float s_chain[128];       // exclusive chain prefix
    __shared__ int   s_tile, s_msg;

    const int t = threadIdx.x;
    if (t == 0) s_tile = atomicAdd(&g_ticket, 1);
    __syncthreads();
    const int tile = s_tile;
    const int bh   = tile & (BH_ - 1);     // chain-interleaved ticket mapping
    const int ti   = tile >> 6;
    const int b    = bh >> 4;
    const int w    = t >> 5;
    const int lane = t & 31;
    const int l0   = ti * TILE_ + w * PPW_;
    const size_t base = ((size_t)bh * L_ + l0) * D_ + lane * 2;
    const float* mrow = mp + b * L_ + l0;

    // ---- Phase A: stream k,v; accumulate warp sums ----
    {
        float sk0 = 0.f, sk1 = 0.f, sv0 = 0.f, sv1 = 0.f;
        #pragma unroll
        for (int i = 0; i < PPW_; ++i) {
            float2 kk = *(const float2*)(kp + base + (size_t)i * D_);
            float2 vv = *(const float2*)(vp + base + (size_t)i * D_);
            float  m  = mrow[i];
            float a0 = phi(kk.x) * m, a1 = phi(kk.y) * m;
            sk0 += a0; sk1 += a1;
            sv0 += a0 * (vv.x * m); sv1 += a1 * (vv.y * m);
        }
        s_warp[w][2 * lane]          = sk0;
        s_warp[w][2 * lane + 1]      = sk1;
        s_warp[w][64 + 2 * lane]     = sv0;
        s_warp[w][64 + 2 * lane + 1] = sv1;
    }
    __syncthreads();

    // ---- Intra-tile scan over the 8 warps (threads 0..127, one channel each) ----
    if (t < 128) {
        float run = 0.f;
        #pragma unroll
        for (int g2 = 0; g2 < WPB_; ++g2) {
            float x = s_warp[g2][t]; s_warp[g2][t] = run; run += x;
        }
        s_tot[t] = run;
        if (ti > 0) g_aggr[(size_t)tile * 128 + t] = run;
        s_chain[t] = 0.f;
    }
    __syncthreads();
    if (ti > 0) {
        __threadfence();
        if (t == 0) atomicExch(&g_flag[tile], 1);
    }

    // ---- Decoupled lookback (single flag per tile; thread 0 polls) ----
    if (ti > 0) {
        volatile int* vf = (volatile int*)g_flag;
        int p = tile - BH_;
        for (;;) {
            if (t == 0) {
                int f;
                while ((f = vf[p]) == 0) __nanosleep(64);
                s_msg = f;
            }
            __syncthreads();
            const int f = s_msg;
            __threadfence();   // acquire: order payload reads after flag read
            if (f == 2) {
                if (t < 128) s_chain[t] += g_incl[(size_t)p * 128 + t];
                break;
            }
            if (t < 128) s_chain[t] += g_aggr[(size_t)p * 128 + t];
            p -= BH_;
            __syncthreads();
        }
    }
    __syncthreads();

    // ---- Publish inclusive prefix for successors ----
    if (t < 128) g_incl[(size_t)tile * 128 + t] = s_chain[t] + s_tot[t];
    __syncthreads();
    __threadfence();
    if (t == 0) atomicExch(&g_flag[tile], 2);

    // ---- Phase C: re-read own k,v (L2-hot), finish scan, compute z, output ----
    float2 pk  = make_float2(s_chain[2 * lane]      + s_warp[w][2 * lane],
                             s_chain[2 * lane + 1]  + s_warp[w][2 * lane + 1]);
    float2 pkv = make_float2(s_chain[64 + 2 * lane]     + s_warp[w][64 + 2 * lane],
                             s_chain[64 + 2 * lane + 1] + s_warp[w][64 + 2 * lane + 1]);

    #pragma unroll
    for (int i = 0; i < PPW_; ++i) {
        const size_t off = base + (size_t)i * D_;
        float2 kk = *(const float2*)(kp + off);
        float2 vv = *(const float2*)(vp + off);
        float2 qq = *(const float2*)(qp + off);
        float  m  = mrow[i];

        float a0 = phi(kk.x) * m, a1 = phi(kk.y) * m;
        pk.x += a0; pk.y += a1;
        pkv.x += a0 * (vv.x * m); pkv.y += a1 * (vv.y * m);

        float q0 = phi(qq.x), q1 = phi(qq.y);
        float z = q0 * pk.x + q1 * pk.y;
        z += __shfl_xor_sync(0xffffffffu, z, 16);
        z += __shfl_xor_sync(0xffffffffu, z, 8);
        z += __shfl_xor_sync(0xffffffffu, z, 4);
        z += __shfl_xor_sync(0xffffffffu, z, 2);
        z += __shfl_xor_sync(0xffffffffu, z, 1);
        z = (z + EPS_) * m;
        float rz = 1.0f / z;

        float2 o = make_float2(q0 * pkv.x * rz, q1 * pkv.y * rz);
        *(float2*)(op + off) = o;
    }
}

// ---------------------------------------------------------------------------
extern "C" void kernel_launch(void* const* d_in, const int* in_sizes, int n_in,
                              void* d_out, int out_size)
{
    const float* q = (const float*)d_in[0];
    const float* k = (const float*)d_in[1];
    const float* v = (const float*)d_in[2];
    const float* m = (const float*)d_in[3];
    float* out = (float*)d_out;

    la_reset<<<(NBLK_ + 255) / 256, 256>>>();
    la_fused<<<NBLK_, 256>>>(q, k, v, m, out);
}